// round 6
// baseline (speedup 1.0000x reference)
#include <cuda_runtime.h>
#include <cuda_bf16.h>
#include <math.h>

#define ROWS 4096          // B*S = 2*2048
#define DM   1024
#define KW   256           // 1024/4 packed words per row
#define NELEM (ROWS*DM)

typedef unsigned int u32;
typedef unsigned long long ull;

// ------------------------- static device scratch (no allocs) -------------
__device__ float  g_xn[4][NELEM];       // layernorm outputs (q,k,v,attn)
__device__ u32    g_xq[4][ROWS*KW];     // int8-packed quantized activations
__device__ u32    g_wq[4][DM*KW];       // int8-packed sign weights
__device__ float  g_proj[3][NELEM];     // qp/kp/vp projections (fp32)
__device__ float  g_att[NELEM];         // attention output (concat heads)
__device__ double g_wpart[4][256][2];   // weight-stat partials (double)
__device__ double g_wmean[4];
__device__ float  g_wbeta[4];
__device__ u32    g_absmax[4];          // float bits, atomicMax as uint
__device__ u32    g_maskbits[ROWS*64];  // bit-packed mask, 2048 bits/row

// ------------------------- f32x2 packed helpers --------------------------
__device__ __forceinline__ ull pk2(float lo, float hi){
  ull r; asm("mov.b64 %0,{%1,%2};" : "=l"(r) : "f"(lo), "f"(hi)); return r;
}
__device__ __forceinline__ float2 upk2(ull v){
  float2 f; asm("mov.b64 {%0,%1},%2;" : "=f"(f.x), "=f"(f.y) : "l"(v)); return f;
}
__device__ __forceinline__ ull f2fma(ull a, ull b, ull c){
  ull r; asm("fma.rn.f32x2 %0,%1,%2,%3;" : "=l"(r) : "l"(a), "l"(b), "l"(c)); return r;
}
__device__ __forceinline__ ull f2mul(ull a, ull b){
  ull r; asm("mul.rn.f32x2 %0,%1,%2;" : "=l"(r) : "l"(a), "l"(b)); return r;
}

__device__ __forceinline__ void cpa16(u32 saddr, const void* g){
  asm volatile("cp.async.cg.shared.global [%0], [%1], 16;" :: "r"(saddr), "l"(g));
}
__device__ __forceinline__ void cpa_commit(){
  asm volatile("cp.async.commit_group;");
}

// ------------------------- reductions ------------------------------------
__device__ __forceinline__ double blockRedD(double v, double* sh){
  #pragma unroll
  for (int o=16;o;o>>=1) v += __shfl_xor_sync(0xffffffffu, v, o);
  if ((threadIdx.x & 31) == 0) sh[threadIdx.x>>5] = v;
  __syncthreads();
  if (threadIdx.x == 0){
    double r = sh[0];
    #pragma unroll
    for (int i=1;i<8;i++) r += sh[i];
    sh[0] = r;
  }
  __syncthreads();
  double r = sh[0];
  __syncthreads();
  return r;
}
__device__ __forceinline__ float blockMaxF(float v, float* sh){
  #pragma unroll
  for (int o=16;o;o>>=1) v = fmaxf(v, __shfl_xor_sync(0xffffffffu, v, o));
  if ((threadIdx.x & 31) == 0) sh[threadIdx.x>>5] = v;
  __syncthreads();
  if (threadIdx.x == 0){
    float r = sh[0];
    #pragma unroll
    for (int i=1;i<8;i++) r = fmaxf(r, sh[i]);
    sh[0] = r;
  }
  __syncthreads();
  float r = sh[0];
  __syncthreads();
  return r;
}

// ------------------------- kernels ---------------------------------------
__global__ void k_init(){
  if (threadIdx.x < 4) g_absmax[threadIdx.x] = 0u;
}

__global__ void k_wstats1(const float* w0, const float* w1,
                          const float* w2, const float* w3){
  const float* w = (blockIdx.y==0)?w0 : (blockIdx.y==1)?w1 : (blockIdx.y==2)?w2 : w3;
  int base = blockIdx.x * 4096;
  double s = 0.0, a = 0.0;
  for (int i = threadIdx.x; i < 4096; i += 256){
    double v = (double)w[base + i]; s += v; a += fabs(v);
  }
  __shared__ double shs[8], sha[8];
  #pragma unroll
  for (int o=16;o;o>>=1){
    s += __shfl_xor_sync(0xffffffffu, s, o);
    a += __shfl_xor_sync(0xffffffffu, a, o);
  }
  if ((threadIdx.x & 31) == 0){ shs[threadIdx.x>>5] = s; sha[threadIdx.x>>5] = a; }
  __syncthreads();
  if (threadIdx.x == 0){
    double S=0.0, A=0.0;
    #pragma unroll
    for (int i=0;i<8;i++){ S += shs[i]; A += sha[i]; }
    g_wpart[blockIdx.y][blockIdx.x][0] = S;
    g_wpart[blockIdx.y][blockIdx.x][1] = A;
  }
}

__global__ void k_wstats2(){
  int wh = blockIdx.x;
  double s = g_wpart[wh][threadIdx.x][0];
  double a = g_wpart[wh][threadIdx.x][1];
  __shared__ double shs[8], sha[8];
  #pragma unroll
  for (int o=16;o;o>>=1){
    s += __shfl_xor_sync(0xffffffffu, s, o);
    a += __shfl_xor_sync(0xffffffffu, a, o);
  }
  if ((threadIdx.x & 31) == 0){ shs[threadIdx.x>>5] = s; sha[threadIdx.x>>5] = a; }
  __syncthreads();
  if (threadIdx.x == 0){
    double S=0.0, A=0.0;
    #pragma unroll
    for (int i=0;i<8;i++){ S += shs[i]; A += sha[i]; }
    g_wmean[wh] = S * (1.0/1048576.0);
    g_wbeta[wh] = (float)(A * (1.0/1048576.0));
  }
}

__device__ __forceinline__ int sgn3d(double x, double mu){
  return (x > mu) ? 1 : ((x < mu) ? -1 : 0);
}

__global__ void k_wquant(const float* w0, const float* w1,
                         const float* w2, const float* w3){
  int wh = blockIdx.y;
  const float* w = (wh==0)?w0 : (wh==1)?w1 : (wh==2)?w2 : w3;
  double mu = g_wmean[wh];
  int o = blockIdx.x;
  float4 v = ((const float4*)(w + (size_t)o*DM))[threadIdx.x];
  int a = sgn3d((double)v.x,mu), b = sgn3d((double)v.y,mu);
  int c = sgn3d((double)v.z,mu), d = sgn3d((double)v.w,mu);
  g_wq[wh][(size_t)o*KW + threadIdx.x] =
      (u32)(a & 0xff) | ((u32)(b & 0xff) << 8) |
      ((u32)(c & 0xff) << 16) | ((u32)(d & 0xff) << 24);
}

// LayerNorm in full double precision; slots 0..2 batched via grid.y.
__device__ __forceinline__ void ln_body(const float* src, int slot, int row){
  __shared__ double shd[8];
  __shared__ float shf[8];
  float4 v = ((const float4*)(src + (size_t)row*DM))[threadIdx.x];
  double s = (double)v.x + (double)v.y + (double)v.z + (double)v.w;
  s = blockRedD(s, shd);
  double mu = s * (1.0/1024.0);
  double ax = (double)v.x - mu, ay = (double)v.y - mu;
  double az = (double)v.z - mu, aw = (double)v.w - mu;
  double ss = ax*ax + ay*ay + az*az + aw*aw;
  ss = blockRedD(ss, shd);
  double var = ss * (1.0/1024.0) + 1e-5;
  double r = 1.0 / sqrt(var);
  float4 o;
  o.x = (float)(ax*r); o.y = (float)(ay*r);
  o.z = (float)(az*r); o.w = (float)(aw*r);
  ((float4*)(g_xn[slot] + (size_t)row*DM))[threadIdx.x] = o;
  float am = fmaxf(fmaxf(fabsf(o.x), fabsf(o.y)), fmaxf(fabsf(o.z), fabsf(o.w)));
  am = blockMaxF(am, shf);
  if (threadIdx.x == 0) atomicMax(&g_absmax[slot], __float_as_uint(am));
}

__global__ void k_ln3(const float* q, const float* k, const float* v){
  int slot = blockIdx.y;
  const float* src = (slot==0)?q : (slot==1)?k : v;
  ln_body(src, slot, blockIdx.x);
}
__global__ void k_ln1(){
  ln_body(g_att, 3, blockIdx.x);
}

__device__ __forceinline__ int qv(float x, float qs){
  int v = (int)rintf(x * qs);        // RN = round half to even, matches jnp.round
  return (v == 128) ? -128 : v;      // int8 wrap of the +128 element
}

__device__ __forceinline__ void quant_body(int slot, int row){
  float mx = __uint_as_float(g_absmax[slot]);
  float qs = 128.0f / mx;
  float4 v = ((const float4*)(g_xn[slot] + (size_t)row*DM))[threadIdx.x];
  int a = qv(v.x,qs), b = qv(v.y,qs), c = qv(v.z,qs), d = qv(v.w,qs);
  g_xq[slot][(size_t)row*KW + threadIdx.x] =
      (u32)(a & 0xff) | ((u32)(b & 0xff) << 8) |
      ((u32)(c & 0xff) << 16) | ((u32)(d & 0xff) << 24);
}
__global__ void k_quant3(){ quant_body(blockIdx.y, blockIdx.x); }
__global__ void k_quant1(){ quant_body(3, blockIdx.x); }

// ---------------- IMMA GEMM: C[r][o] = sum_i xq[r][i]*wq[o][i] (exact) ----
// CTA 128x128, 8 warps, warp tile 32x64, mma.m16n8k32.s8.
// smem rows stride 20 words: fragment LDS banks (20r+c) mod 32 distinct.
__global__ void __launch_bounds__(256) k_gemm(float* Cext, int slot0){
  int slot = slot0 + blockIdx.z;
  const u32* X = g_xq[slot];
  const u32* W = g_wq[slot];
  float* C = (slot < 3) ? g_proj[slot] : Cext;
  int m0 = blockIdx.y * 128, n0 = blockIdx.x * 128;

  __shared__ u32 As[128*20];
  __shared__ u32 Bs[128*20];

  int tid = threadIdx.x;
  int lane = tid & 31, warp = tid >> 5;
  int wm = (warp >> 1) * 32, wn = (warp & 1) * 64;

  int acc[2][8][4];
  #pragma unroll
  for (int mt=0;mt<2;mt++)
    #pragma unroll
    for (int nt=0;nt<8;nt++)
      #pragma unroll
      for (int i=0;i<4;i++) acc[mt][nt][i] = 0;

  for (int kt = 0; kt < 16; kt++){           // 16 chunks of k=64 int8 (16 words)
    #pragma unroll
    for (int l=0;l<2;l++){
      int i = tid + l*256;                   // 0..511
      int row = i >> 2, seg = (i & 3) * 4;
      uint4 xa = *(const uint4*)(X + (size_t)(m0+row)*KW + kt*16 + seg);
      uint4 wb = *(const uint4*)(W + (size_t)(n0+row)*KW + kt*16 + seg);
      *(uint4*)&As[row*20 + seg] = xa;
      *(uint4*)&Bs[row*20 + seg] = wb;
    }
    __syncthreads();
    #pragma unroll
    for (int s=0;s<2;s++){                   // two k32 steps per chunk
      int kw = s*8 + (lane & 3);
      u32 afr[2][4], bfr[8][2];
      #pragma unroll
      for (int mt=0;mt<2;mt++){
        int r = wm + mt*16 + (lane >> 2);
        afr[mt][0] = As[r*20 + kw];
        afr[mt][1] = As[(r+8)*20 + kw];
        afr[mt][2] = As[r*20 + kw + 4];
        afr[mt][3] = As[(r+8)*20 + kw + 4];
      }
      #pragma unroll
      for (int nt=0;nt<8;nt++){
        int r = wn + nt*8 + (lane >> 2);
        bfr[nt][0] = Bs[r*20 + kw];
        bfr[nt][1] = Bs[r*20 + kw + 4];
      }
      #pragma unroll
      for (int mt=0;mt<2;mt++)
        #pragma unroll
        for (int nt=0;nt<8;nt++){
          asm volatile(
            "mma.sync.aligned.m16n8k32.row.col.s32.s8.s8.s32 "
            "{%0,%1,%2,%3}, {%4,%5,%6,%7}, {%8,%9}, {%0,%1,%2,%3};"
            : "+r"(acc[mt][nt][0]), "+r"(acc[mt][nt][1]),
              "+r"(acc[mt][nt][2]), "+r"(acc[mt][nt][3])
            : "r"(afr[mt][0]), "r"(afr[mt][1]), "r"(afr[mt][2]), "r"(afr[mt][3]),
              "r"(bfr[nt][0]), "r"(bfr[nt][1]));
        }
    }
    __syncthreads();
  }

  float mx = __uint_as_float(g_absmax[slot]);
  float scale = (mx / 128.0f) * g_wbeta[slot];   // dequant * beta
  #pragma unroll
  for (int mt=0;mt<2;mt++){
    #pragma unroll
    for (int nt=0;nt<8;nt++){
      int r0 = m0 + wm + mt*16 + (lane >> 2);
      int c0 = n0 + wn + nt*8 + 2*(lane & 3);
      float2 v0, v1;
      v0.x = (float)acc[mt][nt][0] * scale;
      v0.y = (float)acc[mt][nt][1] * scale;
      v1.x = (float)acc[mt][nt][2] * scale;
      v1.y = (float)acc[mt][nt][3] * scale;
      *(float2*)(C + (size_t)r0*DM + c0)     = v0;
      *(float2*)(C + (size_t)(r0+8)*DM + c0) = v1;
    }
  }
}

__global__ void k_maskpack(const int* mask){
  int row = blockIdx.x;                 // b*2048 + q
  int lane = threadIdx.x & 31, wd = threadIdx.x >> 5;
  for (int w8 = 0; w8 < 8; w8++){
    int kk = w8*256 + threadIdx.x;
    int mv = mask[(size_t)row*2048 + kk];
    u32 bits = __ballot_sync(0xffffffffu, mv != 0);
    if (lane == 0) g_maskbits[(size_t)row*64 + w8*8 + wd] = bits;
  }
}

// Flash attention, fp32 via packed f32x2. Two threads per query (dk split
// 32/32), 256 threads = 128 queries per CTA, cp.async double-buffered K/V.
__global__ void __launch_bounds__(256,2) k_flash(){
  extern __shared__ float fsm[];        // [2][64][64] K then [2][64][64] V
  float* KS = fsm;                      // 8192 floats
  float* VS = fsm + 8192;

  int tid = threadIdx.x;
  int qloc = tid >> 1, hf = tid & 1;
  int qt = blockIdx.x & 15;
  int h  = (blockIdx.x >> 4) & 15;
  int b  = blockIdx.x >> 8;
  int q  = qt*128 + qloc;
  size_t qoff = ((size_t)(b*2048 + q))*DM + h*64 + hf*32;
  const float* QP = g_proj[0];
  const float* KP = g_proj[1];
  const float* VP = g_proj[2];

  u32 ks_base = (u32)__cvta_generic_to_shared(KS);
  u32 vs_base = (u32)__cvta_generic_to_shared(VS);

  ull q2[16];
  {
    const float4* qp = (const float4*)(QP + qoff);
    #pragma unroll
    for (int t=0;t<8;t++){
      float4 f = qp[t];
      q2[2*t]   = pk2(f.x*0.125f, f.y*0.125f);   // fold 1/sqrt(64) into q
      q2[2*t+1] = pk2(f.z*0.125f, f.w*0.125f);
    }
  }
  ull acc2[16];
  #pragma unroll
  for (int t=0;t<16;t++) acc2[t] = 0ull;
  float m = -1e30f, s = 0.f;

  const u32* mbase = g_maskbits + (size_t)(b*2048 + q)*64;

  // prologue: load tile 0 into buffer 0
  {
    #pragma unroll
    for (int l=0;l<4;l++){
      int i = tid + l*256;               // 0..1023
      int row = i >> 4, c = (i & 15) * 4;
      size_t goff = ((size_t)(b*2048 + row))*DM + h*64 + c;
      u32 soff = (u32)((row*64 + c) * 4);
      cpa16(ks_base + soff, KP + goff);
      cpa16(vs_base + soff, VP + goff);
    }
    cpa_commit();
  }

  for (int kt = 0; kt < 32; kt++){
    int buf = kt & 1;
    if (kt < 31){
      int nb = buf ^ 1;
      #pragma unroll
      for (int l=0;l<4;l++){
        int i = tid + l*256;
        int row = i >> 4, c = (i & 15) * 4;
        size_t goff = ((size_t)(b*2048 + (kt+1)*64 + row))*DM + h*64 + c;
        u32 soff = (u32)(((nb*64 + row)*64 + c) * 4);
        cpa16(ks_base + soff, KP + goff);
        cpa16(vs_base + soff, VP + goff);
      }
      cpa_commit();
      asm volatile("cp.async.wait_group 1;");
    } else {
      asm volatile("cp.async.wait_group 0;");
    }
    __syncthreads();

    const float* kbuf = KS + buf*4096;
    const float* vbuf = VS + buf*4096;
    int k0 = kt*64;

    #pragma unroll 1
    for (int j0 = 0; j0 < 64; j0 += 8){
      u32 mb = mbase[(k0 + j0) >> 5] >> (j0 & 31);
      float lg[8];
      #pragma unroll
      for (int jj=0;jj<8;jj++){
        const ull* kp = (const ull*)(kbuf + (j0+jj)*64 + hf*32);
        ull d0 = 0ull, d1 = 0ull;
        #pragma unroll
        for (int t=0;t<8;t++){
          d0 = f2fma(q2[2*t],   kp[2*t],   d0);
          d1 = f2fma(q2[2*t+1], kp[2*t+1], d1);
        }
        float2 a = upk2(d0), c = upk2(d1);
        float half = (a.x + a.y) + (c.x + c.y);
        float lv = half + __shfl_xor_sync(0xffffffffu, half, 1);
        lg[jj] = ((mb >> jj) & 1u) ? lv : -1e9f;
      }
      float cm = lg[0];
      #pragma unroll
      for (int jj=1;jj<8;jj++) cm = fmaxf(cm, lg[jj]);
      float mn = fmaxf(m, cm);
      float r = __expf(m - mn);
      float p[8]; float ps = 0.f;
      #pragma unroll
      for (int jj=0;jj<8;jj++){ p[jj] = __expf(lg[jj] - mn); ps += p[jj]; }
      s = s * r + ps;
      ull rr = pk2(r, r);
      #pragma unroll
      for (int t=0;t<16;t++) acc2[t] = f2mul(acc2[t], rr);
      #pragma unroll
      for (int jj=0;jj<8;jj++){
        ull pp = pk2(p[jj], p[jj]);
        const ull* vp = (const ull*)(vbuf + (j0+jj)*64 + hf*32);
        #pragma unroll
        for (int t=0;t<16;t++) acc2[t] = f2fma(pp, vp[t], acc2[t]);
      }
      m = mn;
    }
    __syncthreads();
  }
  float inv = 1.0f / s;
  float* orow = g_att + qoff;
  #pragma unroll
  for (int t=0;t<16;t++){
    float2 f = upk2(acc2[t]);
    f.x *= inv; f.y *= inv;
    *(float2*)(orow + 2*t) = f;
  }
}

// ------------------------- launcher --------------------------------------
extern "C" void kernel_launch(void* const* d_in, const int* in_sizes, int n_in,
                              void* d_out, int out_size){
  const float* q   = (const float*)d_in[0];
  const float* k   = (const float*)d_in[1];
  const float* v   = (const float*)d_in[2];
  const int*  mask = (const int*)  d_in[3];
  const float* w0  = (const float*)d_in[4];  // wq_w
  const float* w1  = (const float*)d_in[5];  // wk_w
  const float* w2  = (const float*)d_in[6];  // wv_w
  const float* w3  = (const float*)d_in[7];  // w0_w
  float* out = (float*)d_out;

  static int smem_set = 0;
  if (!smem_set){
    cudaFuncSetAttribute(k_flash, cudaFuncAttributeMaxDynamicSharedMemorySize, 65536);
    smem_set = 1;
  }

  k_init<<<1,32>>>();
  k_wstats1<<<dim3(256,4),256>>>(w0,w1,w2,w3);
  k_wstats2<<<4,256>>>();
  k_wquant<<<dim3(1024,4),256>>>(w0,w1,w2,w3);

  k_ln3<<<dim3(4096,3),256>>>(q,k,v);
  k_quant3<<<dim3(4096,3),256>>>();

  k_gemm<<<dim3(8,32,3),256>>>(nullptr,0);   // qp, kp, vp projections

  k_maskpack<<<4096,256>>>(mask);
  k_flash<<<512,256,65536>>>();

  k_ln1<<<4096,256>>>();
  k_quant1<<<4096,256>>>();
  k_gemm<<<dim3(8,32,1),256>>>(out,3);       // output projection -> d_out
}

// round 7
// speedup vs baseline: 1.5533x; 1.5533x over previous
#include <cuda_runtime.h>
#include <cuda_bf16.h>
#include <math.h>

#define ROWS 4096          // B*S = 2*2048
#define DM   1024
#define KW   256           // 1024/4 packed words per row
#define NELEM (ROWS*DM)

typedef unsigned int u32;
typedef unsigned long long ull;

// ------------------------- static device scratch (no allocs) -------------
__device__ float  g_xn[4][NELEM];       // layernorm outputs (q,k,v,attn)
__device__ u32    g_xq[4][ROWS*KW];     // int8-packed quantized activations
__device__ u32    g_wq[4][DM*KW];       // int8-packed sign weights
__device__ float  g_proj[3][NELEM];     // qp/kp/vp projections (fp32)
__device__ float  g_att[NELEM];         // attention output (concat heads)
__device__ double g_wpart[4][256][2];   // weight-stat partials (double)
__device__ double g_wmean[4];
__device__ float  g_wbeta[4];
__device__ u32    g_absmax[4];          // float bits, atomicMax as uint
__device__ u32    g_maskbits[ROWS*64];  // bit-packed mask, 2048 bits/row

// ------------------------- f32x2 packed helpers --------------------------
__device__ __forceinline__ ull pk2(float lo, float hi){
  ull r; asm("mov.b64 %0,{%1,%2};" : "=l"(r) : "f"(lo), "f"(hi)); return r;
}
__device__ __forceinline__ float2 upk2(ull v){
  float2 f; asm("mov.b64 {%0,%1},%2;" : "=f"(f.x), "=f"(f.y) : "l"(v)); return f;
}
__device__ __forceinline__ ull f2fma(ull a, ull b, ull c){
  ull r; asm("fma.rn.f32x2 %0,%1,%2,%3;" : "=l"(r) : "l"(a), "l"(b), "l"(c)); return r;
}
__device__ __forceinline__ ull f2mul(ull a, ull b){
  ull r; asm("mul.rn.f32x2 %0,%1,%2;" : "=l"(r) : "l"(a), "l"(b)); return r;
}

__device__ __forceinline__ void cpa16(u32 saddr, const void* g){
  asm volatile("cp.async.cg.shared.global [%0], [%1], 16;" :: "r"(saddr), "l"(g));
}
__device__ __forceinline__ void cpa_commit(){
  asm volatile("cp.async.commit_group;");
}

// ------------------------- reductions ------------------------------------
__device__ __forceinline__ double blockRedD(double v, double* sh){
  #pragma unroll
  for (int o=16;o;o>>=1) v += __shfl_xor_sync(0xffffffffu, v, o);
  if ((threadIdx.x & 31) == 0) sh[threadIdx.x>>5] = v;
  __syncthreads();
  if (threadIdx.x == 0){
    double r = sh[0];
    #pragma unroll
    for (int i=1;i<8;i++) r += sh[i];
    sh[0] = r;
  }
  __syncthreads();
  double r = sh[0];
  __syncthreads();
  return r;
}
__device__ __forceinline__ float blockMaxF(float v, float* sh){
  #pragma unroll
  for (int o=16;o;o>>=1) v = fmaxf(v, __shfl_xor_sync(0xffffffffu, v, o));
  if ((threadIdx.x & 31) == 0) sh[threadIdx.x>>5] = v;
  __syncthreads();
  if (threadIdx.x == 0){
    float r = sh[0];
    #pragma unroll
    for (int i=1;i<8;i++) r = fmaxf(r, sh[i]);
    sh[0] = r;
  }
  __syncthreads();
  float r = sh[0];
  __syncthreads();
  return r;
}

// ------------------------- kernels ---------------------------------------
__global__ void k_wstats1(const float* w0, const float* w1,
                          const float* w2, const float* w3){
  // fold absmax init here (runs before any k_ln)
  if (blockIdx.x == 0 && blockIdx.y == 0 && threadIdx.x < 4)
    g_absmax[threadIdx.x] = 0u;
  const float* w = (blockIdx.y==0)?w0 : (blockIdx.y==1)?w1 : (blockIdx.y==2)?w2 : w3;
  int base = blockIdx.x * 4096;
  double s = 0.0, a = 0.0;
  for (int i = threadIdx.x; i < 4096; i += 256){
    double v = (double)w[base + i]; s += v; a += fabs(v);
  }
  __shared__ double shs[8], sha[8];
  #pragma unroll
  for (int o=16;o;o>>=1){
    s += __shfl_xor_sync(0xffffffffu, s, o);
    a += __shfl_xor_sync(0xffffffffu, a, o);
  }
  if ((threadIdx.x & 31) == 0){ shs[threadIdx.x>>5] = s; sha[threadIdx.x>>5] = a; }
  __syncthreads();
  if (threadIdx.x == 0){
    double S=0.0, A=0.0;
    #pragma unroll
    for (int i=0;i<8;i++){ S += shs[i]; A += sha[i]; }
    g_wpart[blockIdx.y][blockIdx.x][0] = S;
    g_wpart[blockIdx.y][blockIdx.x][1] = A;
  }
}

__global__ void k_wstats2(){
  int wh = blockIdx.x;
  double s = g_wpart[wh][threadIdx.x][0];
  double a = g_wpart[wh][threadIdx.x][1];
  __shared__ double shs[8], sha[8];
  #pragma unroll
  for (int o=16;o;o>>=1){
    s += __shfl_xor_sync(0xffffffffu, s, o);
    a += __shfl_xor_sync(0xffffffffu, a, o);
  }
  if ((threadIdx.x & 31) == 0){ shs[threadIdx.x>>5] = s; sha[threadIdx.x>>5] = a; }
  __syncthreads();
  if (threadIdx.x == 0){
    double S=0.0, A=0.0;
    #pragma unroll
    for (int i=0;i<8;i++){ S += shs[i]; A += sha[i]; }
    g_wmean[wh] = S * (1.0/1048576.0);
    g_wbeta[wh] = (float)(A * (1.0/1048576.0));
  }
}

__device__ __forceinline__ int sgn3d(double x, double mu){
  return (x > mu) ? 1 : ((x < mu) ? -1 : 0);
}

__global__ void k_wquant(const float* w0, const float* w1,
                         const float* w2, const float* w3){
  int wh = blockIdx.y;
  const float* w = (wh==0)?w0 : (wh==1)?w1 : (wh==2)?w2 : w3;
  double mu = g_wmean[wh];
  int o = blockIdx.x;
  float4 v = ((const float4*)(w + (size_t)o*DM))[threadIdx.x];
  int a = sgn3d((double)v.x,mu), b = sgn3d((double)v.y,mu);
  int c = sgn3d((double)v.z,mu), d = sgn3d((double)v.w,mu);
  g_wq[wh][(size_t)o*KW + threadIdx.x] =
      (u32)(a & 0xff) | ((u32)(b & 0xff) << 8) |
      ((u32)(c & 0xff) << 16) | ((u32)(d & 0xff) << 24);
}

// LayerNorm in full double precision; slots 0..2 batched via grid.y.
__device__ __forceinline__ void ln_body(const float* src, int slot, int row){
  __shared__ double shd[8];
  __shared__ float shf[8];
  float4 v = ((const float4*)(src + (size_t)row*DM))[threadIdx.x];
  double s = (double)v.x + (double)v.y + (double)v.z + (double)v.w;
  s = blockRedD(s, shd);
  double mu = s * (1.0/1024.0);
  double ax = (double)v.x - mu, ay = (double)v.y - mu;
  double az = (double)v.z - mu, aw = (double)v.w - mu;
  double ss = ax*ax + ay*ay + az*az + aw*aw;
  ss = blockRedD(ss, shd);
  double var = ss * (1.0/1024.0) + 1e-5;
  double r = 1.0 / sqrt(var);
  float4 o;
  o.x = (float)(ax*r); o.y = (float)(ay*r);
  o.z = (float)(az*r); o.w = (float)(aw*r);
  ((float4*)(g_xn[slot] + (size_t)row*DM))[threadIdx.x] = o;
  float am = fmaxf(fmaxf(fabsf(o.x), fabsf(o.y)), fmaxf(fabsf(o.z), fabsf(o.w)));
  am = blockMaxF(am, shf);
  if (threadIdx.x == 0) atomicMax(&g_absmax[slot], __float_as_uint(am));
}

__global__ void k_ln3(const float* q, const float* k, const float* v){
  int slot = blockIdx.y;
  const float* src = (slot==0)?q : (slot==1)?k : v;
  ln_body(src, slot, blockIdx.x);
}
__global__ void k_ln1(){
  ln_body(g_att, 3, blockIdx.x);
}

__device__ __forceinline__ int qv(float x, float qs){
  int v = (int)rintf(x * qs);        // RN = round half to even, matches jnp.round
  return (v == 128) ? -128 : v;      // int8 wrap of the +128 element
}

__device__ __forceinline__ void quant_body(int slot, int row){
  float mx = __uint_as_float(g_absmax[slot]);
  float qs = 128.0f / mx;
  float4 v = ((const float4*)(g_xn[slot] + (size_t)row*DM))[threadIdx.x];
  int a = qv(v.x,qs), b = qv(v.y,qs), c = qv(v.z,qs), d = qv(v.w,qs);
  g_xq[slot][(size_t)row*KW + threadIdx.x] =
      (u32)(a & 0xff) | ((u32)(b & 0xff) << 8) |
      ((u32)(c & 0xff) << 16) | ((u32)(d & 0xff) << 24);
}
__global__ void k_quant3(){ quant_body(blockIdx.y, blockIdx.x); }
__global__ void k_quant1(){ quant_body(3, blockIdx.x); }

// ---------------- IMMA GEMM: C[r][o] = sum_i xq[r][i]*wq[o][i] (exact) ----
// CTA 128x128, 8 warps, warp tile 32x64, mma.m16n8k32.s8.
// smem rows stride 20 words: fragment LDS banks (20r+c) mod 32 distinct.
__global__ void __launch_bounds__(256) k_gemm(float* Cext, int slot0){
  int slot = slot0 + blockIdx.z;
  const u32* X = g_xq[slot];
  const u32* W = g_wq[slot];
  float* C = (slot < 3) ? g_proj[slot] : Cext;
  int m0 = blockIdx.y * 128, n0 = blockIdx.x * 128;

  __shared__ u32 As[128*20];
  __shared__ u32 Bs[128*20];

  int tid = threadIdx.x;
  int lane = tid & 31, warp = tid >> 5;
  int wm = (warp >> 1) * 32, wn = (warp & 1) * 64;

  int acc[2][8][4];
  #pragma unroll
  for (int mt=0;mt<2;mt++)
    #pragma unroll
    for (int nt=0;nt<8;nt++)
      #pragma unroll
      for (int i=0;i<4;i++) acc[mt][nt][i] = 0;

  for (int kt = 0; kt < 16; kt++){           // 16 chunks of k=64 int8 (16 words)
    #pragma unroll
    for (int l=0;l<2;l++){
      int i = tid + l*256;                   // 0..511
      int row = i >> 2, seg = (i & 3) * 4;
      uint4 xa = *(const uint4*)(X + (size_t)(m0+row)*KW + kt*16 + seg);
      uint4 wb = *(const uint4*)(W + (size_t)(n0+row)*KW + kt*16 + seg);
      *(uint4*)&As[row*20 + seg] = xa;
      *(uint4*)&Bs[row*20 + seg] = wb;
    }
    __syncthreads();
    #pragma unroll
    for (int s=0;s<2;s++){                   // two k32 steps per chunk
      int kw = s*8 + (lane & 3);
      u32 afr[2][4], bfr[8][2];
      #pragma unroll
      for (int mt=0;mt<2;mt++){
        int r = wm + mt*16 + (lane >> 2);
        afr[mt][0] = As[r*20 + kw];
        afr[mt][1] = As[(r+8)*20 + kw];
        afr[mt][2] = As[r*20 + kw + 4];
        afr[mt][3] = As[(r+8)*20 + kw + 4];
      }
      #pragma unroll
      for (int nt=0;nt<8;nt++){
        int r = wn + nt*8 + (lane >> 2);
        bfr[nt][0] = Bs[r*20 + kw];
        bfr[nt][1] = Bs[r*20 + kw + 4];
      }
      #pragma unroll
      for (int mt=0;mt<2;mt++)
        #pragma unroll
        for (int nt=0;nt<8;nt++){
          asm volatile(
            "mma.sync.aligned.m16n8k32.row.col.s32.s8.s8.s32 "
            "{%0,%1,%2,%3}, {%4,%5,%6,%7}, {%8,%9}, {%0,%1,%2,%3};"
            : "+r"(acc[mt][nt][0]), "+r"(acc[mt][nt][1]),
              "+r"(acc[mt][nt][2]), "+r"(acc[mt][nt][3])
            : "r"(afr[mt][0]), "r"(afr[mt][1]), "r"(afr[mt][2]), "r"(afr[mt][3]),
              "r"(bfr[nt][0]), "r"(bfr[nt][1]));
        }
    }
    __syncthreads();
  }

  float mx = __uint_as_float(g_absmax[slot]);
  float scale = (mx / 128.0f) * g_wbeta[slot];   // dequant * beta
  #pragma unroll
  for (int mt=0;mt<2;mt++){
    #pragma unroll
    for (int nt=0;nt<8;nt++){
      int r0 = m0 + wm + mt*16 + (lane >> 2);
      int c0 = n0 + wn + nt*8 + 2*(lane & 3);
      float2 v0, v1;
      v0.x = (float)acc[mt][nt][0] * scale;
      v0.y = (float)acc[mt][nt][1] * scale;
      v1.x = (float)acc[mt][nt][2] * scale;
      v1.y = (float)acc[mt][nt][3] * scale;
      *(float2*)(C + (size_t)r0*DM + c0)     = v0;
      *(float2*)(C + (size_t)(r0+8)*DM + c0) = v1;
    }
  }
}

__global__ void k_maskpack(const int* mask){
  int row = blockIdx.x;                 // b*2048 + q
  int lane = threadIdx.x & 31, wd = threadIdx.x >> 5;
  for (int w8 = 0; w8 < 8; w8++){
    int kk = w8*256 + threadIdx.x;
    int mv = mask[(size_t)row*2048 + kk];
    u32 bits = __ballot_sync(0xffffffffu, mv != 0);
    if (lane == 0) g_maskbits[(size_t)row*64 + w8*8 + wd] = bits;
  }
}

// Flash attention, fp32 via packed f32x2. One query per thread, LDS.128
// K/V tile reads, cp.async double-buffered tiles, __expf softmax.
__global__ void __launch_bounds__(128,2) k_flash(){
  extern __shared__ float fsm[];        // [2][64][64] K then [2][64][64] V
  float* KS = fsm;                      // 8192 floats
  float* VS = fsm + 8192;

  int tid = threadIdx.x;
  int qt = blockIdx.x & 15;
  int h  = (blockIdx.x >> 4) & 15;
  int b  = blockIdx.x >> 8;
  int q  = qt*128 + tid;
  size_t qoff = ((size_t)(b*2048 + q))*DM + h*64;
  const float* QP = g_proj[0];
  const float* KP = g_proj[1];
  const float* VP = g_proj[2];

  u32 ks_base = (u32)__cvta_generic_to_shared(KS);
  u32 vs_base = (u32)__cvta_generic_to_shared(VS);

  ull q2[32];
  {
    const float4* qp = (const float4*)(QP + qoff);
    #pragma unroll
    for (int t=0;t<16;t++){
      float4 f = qp[t];
      q2[2*t]   = pk2(f.x*0.125f, f.y*0.125f);   // fold 1/sqrt(64) into q
      q2[2*t+1] = pk2(f.z*0.125f, f.w*0.125f);
    }
  }
  ull acc2[32];
  #pragma unroll
  for (int t=0;t<32;t++) acc2[t] = 0ull;
  float m = -1e30f, s = 0.f;

  const u32* mbase = g_maskbits + (size_t)(b*2048 + q)*64;

  // prologue: tile 0 -> buffer 0 (64 rows x 16 float4 each for K and V)
  #pragma unroll
  for (int l=0;l<8;l++){
    int i = tid + l*128;               // 0..1023
    int row = i >> 4, c = (i & 15) * 4;
    size_t goff = ((size_t)(b*2048 + row))*DM + h*64 + c;
    u32 soff = (u32)((row*64 + c) * 4);
    cpa16(ks_base + soff, KP + goff);
    cpa16(vs_base + soff, VP + goff);
  }
  cpa_commit();

  for (int kt = 0; kt < 32; kt++){
    int buf = kt & 1;
    if (kt < 31){
      int nb = buf ^ 1;
      #pragma unroll
      for (int l=0;l<8;l++){
        int i = tid + l*128;
        int row = i >> 4, c = (i & 15) * 4;
        size_t goff = ((size_t)(b*2048 + (kt+1)*64 + row))*DM + h*64 + c;
        u32 soff = (u32)(((nb*64 + row)*64 + c) * 4);
        cpa16(ks_base + soff, KP + goff);
        cpa16(vs_base + soff, VP + goff);
      }
      cpa_commit();
      asm volatile("cp.async.wait_group 1;");
    } else {
      asm volatile("cp.async.wait_group 0;");
    }
    __syncthreads();

    const float* kbuf = KS + buf*4096;
    const float* vbuf = VS + buf*4096;
    int k0 = kt*64;

    #pragma unroll 1
    for (int j0 = 0; j0 < 64; j0 += 8){
      u32 mb = mbase[(k0 + j0) >> 5] >> (j0 & 31);
      float lg[8];
      #pragma unroll
      for (int jj=0;jj<8;jj++){
        const ulonglong2* kp2 = (const ulonglong2*)(kbuf + (j0+jj)*64);
        ull d0 = 0ull, d1 = 0ull;
        #pragma unroll
        for (int t=0;t<16;t++){
          ulonglong2 kk = kp2[t];          // LDS.128 broadcast
          d0 = f2fma(q2[2*t],   kk.x, d0);
          d1 = f2fma(q2[2*t+1], kk.y, d1);
        }
        float2 a = upk2(d0), c2 = upk2(d1);
        float lv = (a.x + a.y) + (c2.x + c2.y);
        lg[jj] = ((mb >> jj) & 1u) ? lv : -1e9f;
      }
      float cm = lg[0];
      #pragma unroll
      for (int jj=1;jj<8;jj++) cm = fmaxf(cm, lg[jj]);
      if (cm > m){                        // rescale only when max moves
        float mn = cm;
        float r = __expf(m - mn);
        s *= r;
        ull rr = pk2(r, r);
        #pragma unroll
        for (int t=0;t<32;t++) acc2[t] = f2mul(acc2[t], rr);
        m = mn;
      }
      float p[8]; float ps = 0.f;
      #pragma unroll
      for (int jj=0;jj<8;jj++){ p[jj] = __expf(lg[jj] - m); ps += p[jj]; }
      s += ps;
      #pragma unroll
      for (int jj=0;jj<8;jj++){
        ull pp = pk2(p[jj], p[jj]);
        const ulonglong2* vp2 = (const ulonglong2*)(vbuf + (j0+jj)*64);
        #pragma unroll
        for (int t=0;t<16;t++){
          ulonglong2 vv = vp2[t];          // LDS.128 broadcast
          acc2[2*t]   = f2fma(pp, vv.x, acc2[2*t]);
          acc2[2*t+1] = f2fma(pp, vv.y, acc2[2*t+1]);
        }
      }
    }
    __syncthreads();
  }
  float inv = 1.0f / s;
  float* orow = g_att + qoff;
  #pragma unroll
  for (int t=0;t<32;t++){
    float2 f = upk2(acc2[t]);
    f.x *= inv; f.y *= inv;
    *(float2*)(orow + 2*t) = f;
  }
}

// ------------------------- launcher --------------------------------------
extern "C" void kernel_launch(void* const* d_in, const int* in_sizes, int n_in,
                              void* d_out, int out_size){
  const float* q   = (const float*)d_in[0];
  const float* k   = (const float*)d_in[1];
  const float* v   = (const float*)d_in[2];
  const int*  mask = (const int*)  d_in[3];
  const float* w0  = (const float*)d_in[4];  // wq_w
  const float* w1  = (const float*)d_in[5];  // wk_w
  const float* w2  = (const float*)d_in[6];  // wv_w
  const float* w3  = (const float*)d_in[7];  // w0_w
  float* out = (float*)d_out;

  static int smem_set = 0;
  if (!smem_set){
    cudaFuncSetAttribute(k_flash, cudaFuncAttributeMaxDynamicSharedMemorySize, 65536);
    smem_set = 1;
  }

  k_wstats1<<<dim3(256,4),256>>>(w0,w1,w2,w3);   // (0) also inits absmax
  k_wstats2<<<4,256>>>();                        // (1)
  k_wquant<<<dim3(1024,4),256>>>(w0,w1,w2,w3);   // (2)

  k_ln3<<<dim3(4096,3),256>>>(q,k,v);            // (3)
  k_quant3<<<dim3(4096,3),256>>>();              // (4)

  k_gemm<<<dim3(8,32,3),256>>>(nullptr,0);       // (5) <- ncu -s 5 profiles this

  k_maskpack<<<4096,256>>>(mask);                // (6)
  k_flash<<<512,128,65536>>>();                  // (7)

  k_ln1<<<4096,256>>>();                         // (8)
  k_quant1<<<4096,256>>>();                      // (9)
  k_gemm<<<dim3(8,32,1),256>>>(out,3);           // (10)
}